// round 2
// baseline (speedup 1.0000x reference)
#include <cuda_runtime.h>
#include <cuda_bf16.h>
#include <cstdint>
#include <cstddef>

// ---------------------------------------------------------------------------
// DependencyParsingNetwork: embed -> 2-layer biLSTM (T=2048, H=256) -> masked
// tanh score matrix [T,T].
//
// Pipeline (one stream, graph-capturable, no allocations):
//   1. gemm_bias: pre0f/pre0b = gather(E,idx) @ Wih0{f,b}^T + b   [2048,1024]
//   2. lstm_layer (cluster of 8 CTAs per direction, 2 clusters):
//        x1[t] = concat(h0f[t], h0b[t])                           [2048,512]
//   3. gemm_bias: pre1f/pre1b = x1 @ Wih1{f,b}^T + b              [2048,1024]
//   4. lstm_layer: x2 = concat(h1f, h1b)                          [2048,512]
//   5. heads: s_head = x2 @ Wm[:512], s_dep = x2 @ Wm[512:]
//   6. scores: out[i,j] = (j>i) ? tanh(s_head[i]+s_dep[j]+bm) : 0
// ---------------------------------------------------------------------------

#define TLEN 2048
#define HID  256
#define CSZ  8      // cluster size (CTAs per direction)

// ------------------------- device scratch (static) -------------------------
__device__ float g_pre0f[TLEN * 1024];
__device__ float g_pre0b[TLEN * 1024];
__device__ float g_pre1f[TLEN * 1024];
__device__ float g_pre1b[TLEN * 1024];
__device__ float g_x1[TLEN * 512];
__device__ float g_x2[TLEN * 512];
__device__ float g_sh[TLEN];
__device__ float g_sd[TLEN];

// ------------------------------ helpers ------------------------------------
__device__ __forceinline__ uint32_t smem_u32(const void* p) {
    uint32_t a;
    asm("{ .reg .u64 t; cvta.to.shared.u64 t, %1; cvt.u32.u64 %0, t; }"
        : "=r"(a) : "l"(p));
    return a;
}

#define CLUSTER_SYNC() do { \
    asm volatile("barrier.cluster.arrive.aligned;" ::: "memory"); \
    asm volatile("barrier.cluster.wait.aligned;" ::: "memory"); \
} while (0)

__device__ __forceinline__ float sigmoidf_(float x) {
    float e = __expf(-fabsf(x));
    float s = __fdividef(1.f, 1.f + e);
    return x >= 0.f ? s : 1.f - s;
}
__device__ __forceinline__ float tanhf_(float x) {
    float e = __expf(-2.f * fabsf(x));
    float t = __fdividef(1.f - e, 1.f + e);
    return x >= 0.f ? t : -t;
}

// ------------------------------ GEMM ---------------------------------------
// out[M,N] = A[M,K] @ W[N,K]^T + bias[N]
// A row m = (idx ? E[idx[m]] : X[m]).  M,N multiples of 64, K multiple of 16.
#define BM 64
#define BN 64
#define BK 16

__global__ __launch_bounds__(256) void gemm_bias_kernel(
    const float* __restrict__ X, const int* __restrict__ idx,
    const float* __restrict__ E, const float* __restrict__ W,
    const float* __restrict__ bias, float* __restrict__ out,
    int M, int N, int K)
{
    __shared__ __align__(16) float As[BK][BM + 4];
    __shared__ __align__(16) float Bs[BK][BN + 4];

    int tid = threadIdx.x;
    int m0 = blockIdx.y * BM, n0 = blockIdx.x * BN;
    int lrow = tid >> 2;          // 0..63
    int lcol = (tid & 3) * 4;     // 0,4,8,12
    int tx = tid & 15, ty = tid >> 4;

    float acc[4][4] = {};

    const float* Arow;
    if (idx) Arow = E + (size_t)idx[m0 + lrow] * K;
    else     Arow = X + (size_t)(m0 + lrow) * K;
    const float* Brow = W + (size_t)(n0 + lrow) * K;

    for (int k0 = 0; k0 < K; k0 += BK) {
        float4 av = *(const float4*)(Arow + k0 + lcol);
        float4 bv = *(const float4*)(Brow + k0 + lcol);
        As[lcol + 0][lrow] = av.x; As[lcol + 1][lrow] = av.y;
        As[lcol + 2][lrow] = av.z; As[lcol + 3][lrow] = av.w;
        Bs[lcol + 0][lrow] = bv.x; Bs[lcol + 1][lrow] = bv.y;
        Bs[lcol + 2][lrow] = bv.z; Bs[lcol + 3][lrow] = bv.w;
        __syncthreads();

        #pragma unroll
        for (int kk = 0; kk < BK; kk++) {
            float4 a = *(const float4*)&As[kk][ty * 4];
            float4 b = *(const float4*)&Bs[kk][tx * 4];
            acc[0][0] += a.x * b.x; acc[0][1] += a.x * b.y;
            acc[0][2] += a.x * b.z; acc[0][3] += a.x * b.w;
            acc[1][0] += a.y * b.x; acc[1][1] += a.y * b.y;
            acc[1][2] += a.y * b.z; acc[1][3] += a.y * b.w;
            acc[2][0] += a.z * b.x; acc[2][1] += a.z * b.y;
            acc[2][2] += a.z * b.z; acc[2][3] += a.z * b.w;
            acc[3][0] += a.w * b.x; acc[3][1] += a.w * b.y;
            acc[3][2] += a.w * b.z; acc[3][3] += a.w * b.w;
        }
        __syncthreads();
    }

    #pragma unroll
    for (int i = 0; i < 4; i++) {
        int m = m0 + ty * 4 + i;
        #pragma unroll
        for (int jj = 0; jj < 4; jj++) {
            int n = n0 + tx * 4 + jj;
            out[(size_t)m * N + n] = acc[i][jj] + bias[n];
        }
    }
}

// --------------------------- LSTM recurrence --------------------------------
// One cluster of CSZ CTAs per direction (grid = 2*CSZ blocks).
// CTA rank owns hidden units [32*rank, 32*rank+32); holds its 128 gate rows of
// Whh (4 gates x 32 units x 256) in REGISTERS (128 floats / thread, 2 threads
// per row). Per step: matvec -> gates -> c,h update -> push h slice to every
// CTA's double-buffered hbuf via st.shared::cluster -> barrier.cluster.
__global__ void __cluster_dims__(CSZ, 1, 1) __launch_bounds__(256, 1)
lstm_layer_kernel(const float* __restrict__ pre_f, const float* __restrict__ pre_b,
                  const float* __restrict__ Whh_f, const float* __restrict__ Whh_b,
                  float* __restrict__ out, int ostride)
{
    __shared__ __align__(16) float hbuf[2][HID];
    __shared__ float gates_s[128];

    int tid  = threadIdx.x;
    int rank = blockIdx.x & (CSZ - 1);
    int dir  = blockIdx.x / CSZ;

    const float* pre = dir ? pre_b : pre_f;
    const float* Whh = dir ? Whh_b : Whh_f;
    int off = dir ? HID : 0;

    int row_local = tid >> 1;           // 0..127
    int half = tid & 1;                 // which 128-wide K half
    int gate = row_local >> 5;          // 0..3 (i,f,g,o)
    int jj   = row_local & 31;          // unit within slice
    int gr   = gate * HID + rank * 32 + jj;   // global gate row (0..1023)

    // load this thread's 128 weights into registers
    float4 w4[32];
    const float4* wsrc = (const float4*)(Whh + (size_t)gr * HID + half * 128);
    #pragma unroll
    for (int i = 0; i < 32; i++) w4[i] = wsrc[i];

    hbuf[0][tid] = 0.f;                 // 256 threads, 256 entries
    float c = 0.f;
    CLUSTER_SYNC();                     // h0 visible / inits done everywhere

    int p = 0;
    for (int t = 0; t < TLEN; t++) {
        int tt = dir ? (TLEN - 1 - t) : t;
        float pv = __ldg(&pre[tt * 1024 + gr]);   // issued early, hidden by dots

        const float4* h4 = (const float4*)&hbuf[p][half * 128];
        float ax = 0.f, ay = 0.f, az = 0.f, aw = 0.f;
        #pragma unroll
        for (int i = 0; i < 32; i++) {
            float4 hv = h4[i];
            ax += w4[i].x * hv.x; ay += w4[i].y * hv.y;
            az += w4[i].z * hv.z; aw += w4[i].w * hv.w;
        }
        float dot = (ax + ay) + (az + aw);
        dot += __shfl_xor_sync(0xffffffffu, dot, 1);  // combine the two halves
        if (half == 0) gates_s[row_local] = dot + pv;
        __syncthreads();

        int pn = p ^ 1;
        if (tid < 32) {
            float gi = gates_s[tid];
            float gf = gates_s[32 + tid];
            float gg = gates_s[64 + tid];
            float go = gates_s[96 + tid];
            c = sigmoidf_(gf) * c + sigmoidf_(gi) * tanhf_(gg);
            float h = sigmoidf_(go) * tanhf_(c);
            int u = rank * 32 + tid;
            out[(size_t)tt * ostride + off + u] = h;
            uint32_t laddr = smem_u32(&hbuf[pn][u]);
            #pragma unroll
            for (int r = 0; r < CSZ; r++) {
                uint32_t raddr;
                asm volatile("mapa.shared::cluster.u32 %0, %1, %2;"
                             : "=r"(raddr) : "r"(laddr), "r"(r));
                asm volatile("st.shared::cluster.f32 [%0], %1;"
                             :: "r"(raddr), "f"(h) : "memory");
            }
        }
        CLUSTER_SYNC();   // h for step t visible in every CTA's hbuf[pn]
        p = pn;
    }
}

// ------------------------------ heads --------------------------------------
// s_head[t] = x2[t] . Wm[0:512];  s_dep[t] = x2[t] . Wm[512:1024]
__global__ __launch_bounds__(256) void heads_kernel(
    const float* __restrict__ x2, const float* __restrict__ Wm,
    float* __restrict__ sh, float* __restrict__ sd)
{
    int warp = threadIdx.x >> 5, lane = threadIdx.x & 31;
    int row = blockIdx.x * 8 + warp;
    const float4* xr = (const float4*)(x2 + (size_t)row * 512);
    const float4* wh = (const float4*)(Wm);
    const float4* wd = (const float4*)(Wm + 512);
    float a = 0.f, b = 0.f;
    #pragma unroll 4
    for (int i = lane; i < 128; i += 32) {
        float4 xv = xr[i]; float4 hv = wh[i]; float4 dv = wd[i];
        a += xv.x * hv.x + xv.y * hv.y + xv.z * hv.z + xv.w * hv.w;
        b += xv.x * dv.x + xv.y * dv.y + xv.z * dv.z + xv.w * dv.w;
    }
    #pragma unroll
    for (int o = 16; o; o >>= 1) {
        a += __shfl_xor_sync(0xffffffffu, a, o);
        b += __shfl_xor_sync(0xffffffffu, b, o);
    }
    if (lane == 0) { sh[row] = a; sd[row] = b; }
}

// ------------------------------ scores -------------------------------------
__global__ __launch_bounds__(256) void scores_kernel(
    const float* __restrict__ sh, const float* __restrict__ sd,
    const float* __restrict__ bm, float* __restrict__ out)
{
    float bb = __ldg(bm);
    size_t stride = (size_t)gridDim.x * blockDim.x;
    for (size_t idx = (size_t)blockIdx.x * blockDim.x + threadIdx.x;
         idx < (size_t)TLEN * TLEN; idx += stride) {
        int i  = (int)(idx >> 11);
        int j  = (int)(idx & 2047);
        out[idx] = (j > i) ? tanhf(sh[i] + sd[j] + bb) : 0.f;
    }
}

// ------------------------------ launch -------------------------------------
extern "C" void kernel_launch(void* const* d_in, const int* in_sizes, int n_in,
                              void* d_out, int out_size)
{
    const int*   word_idx = (const int*)  d_in[0];
    const float* E        = (const float*)d_in[1];
    const float* Wih0f    = (const float*)d_in[2];
    const float* Whh0f    = (const float*)d_in[3];
    const float* b0f      = (const float*)d_in[4];
    const float* Wih0b    = (const float*)d_in[5];
    const float* Whh0b    = (const float*)d_in[6];
    const float* b0b      = (const float*)d_in[7];
    const float* Wih1f    = (const float*)d_in[8];
    const float* Whh1f    = (const float*)d_in[9];
    const float* b1f      = (const float*)d_in[10];
    const float* Wih1b    = (const float*)d_in[11];
    const float* Whh1b    = (const float*)d_in[12];
    const float* b1b      = (const float*)d_in[13];
    const float* Wm       = (const float*)d_in[14];
    const float* bm       = (const float*)d_in[15];
    float* out = (float*)d_out;

    float *pre0f, *pre0b, *pre1f, *pre1b, *x1, *x2, *sh, *sd;
    cudaGetSymbolAddress((void**)&pre0f, g_pre0f);
    cudaGetSymbolAddress((void**)&pre0b, g_pre0b);
    cudaGetSymbolAddress((void**)&pre1f, g_pre1f);
    cudaGetSymbolAddress((void**)&pre1b, g_pre1b);
    cudaGetSymbolAddress((void**)&x1,    g_x1);
    cudaGetSymbolAddress((void**)&x2,    g_x2);
    cudaGetSymbolAddress((void**)&sh,    g_sh);
    cudaGetSymbolAddress((void**)&sd,    g_sd);

    dim3 gg(1024 / BN, TLEN / BM);

    // layer 0 input projection (fused embedding gather)
    gemm_bias_kernel<<<gg, 256>>>(nullptr, word_idx, E, Wih0f, b0f, pre0f,
                                  TLEN, 1024, 256);
    gemm_bias_kernel<<<gg, 256>>>(nullptr, word_idx, E, Wih0b, b0b, pre0b,
                                  TLEN, 1024, 256);
    // layer 0 recurrence (fwd + bwd clusters)
    lstm_layer_kernel<<<2 * CSZ, 256>>>(pre0f, pre0b, Whh0f, Whh0b, x1, 512);

    // layer 1 input projection
    gemm_bias_kernel<<<gg, 256>>>(x1, nullptr, nullptr, Wih1f, b1f, pre1f,
                                  TLEN, 1024, 512);
    gemm_bias_kernel<<<gg, 256>>>(x1, nullptr, nullptr, Wih1b, b1b, pre1b,
                                  TLEN, 1024, 512);
    // layer 1 recurrence
    lstm_layer_kernel<<<2 * CSZ, 256>>>(pre1f, pre1b, Whh1f, Whh1b, x2, 512);

    // scoring head
    heads_kernel<<<TLEN / 8, 256>>>(x2, Wm, sh, sd);
    scores_kernel<<<4096, 256>>>(sh, sd, bm, out);
}

// round 4
// speedup vs baseline: 1.0699x; 1.0699x over previous
#include <cuda_runtime.h>
#include <cuda_bf16.h>
#include <cstdint>
#include <cstddef>

// ---------------------------------------------------------------------------
// DependencyParsingNetwork: embed -> 2-layer biLSTM (T=2048, H=256) -> masked
// tanh score matrix [T,T].
//
//   1. gemm_bias2: pre0{f,b} = gather(E,idx) @ Wih0{f,b}^T + b    (one launch)
//   2. lstm_layer: cluster of 8 CTAs per direction; h exchanged via
//      st.async.shared::cluster + mbarrier complete_tx (no barrier.cluster
//      in the loop).
//   3. gemm_bias2: pre1{f,b} = x1 @ Wih1{f,b}^T + b
//   4. lstm_layer -> x2
//   5. heads + masked tanh scores
// ---------------------------------------------------------------------------

#define TLEN 2048
#define HID  256
#define CSZ  8      // cluster size (CTAs per direction)

// ------------------------- device scratch (static) -------------------------
__device__ float g_pre0f[TLEN * 1024];
__device__ float g_pre0b[TLEN * 1024];
__device__ float g_pre1f[TLEN * 1024];
__device__ float g_pre1b[TLEN * 1024];
__device__ float g_x1[TLEN * 512];
__device__ float g_x2[TLEN * 512];
__device__ float g_sh[TLEN];
__device__ float g_sd[TLEN];

// ------------------------------ helpers ------------------------------------
__device__ __forceinline__ uint32_t smem_u32(const void* p) {
    uint32_t a;
    asm("{ .reg .u64 t; cvta.to.shared.u64 t, %1; cvt.u32.u64 %0, t; }"
        : "=r"(a) : "l"(p));
    return a;
}

#define CLUSTER_SYNC() do { \
    asm volatile("barrier.cluster.arrive.aligned;" ::: "memory"); \
    asm volatile("barrier.cluster.wait.aligned;" ::: "memory"); \
} while (0)

__device__ __forceinline__ void mbar_init(uint32_t mbar, uint32_t count) {
    asm volatile("mbarrier.init.shared.b64 [%0], %1;" :: "r"(mbar), "r"(count)
                 : "memory");
}
__device__ __forceinline__ void mbar_expect_tx(uint32_t mbar, uint32_t bytes) {
    asm volatile("mbarrier.arrive.expect_tx.shared.b64 _, [%0], %1;"
                 :: "r"(mbar), "r"(bytes) : "memory");
}
// acquire at cluster scope: data was produced by remote-CTA st.async
__device__ __forceinline__ void mbar_wait_cluster(uint32_t mbar, uint32_t parity) {
    uint32_t done;
    asm volatile(
        "{\n\t.reg .pred p;\n\t"
        "mbarrier.try_wait.parity.acquire.cluster.shared::cta.b64 p, [%1], %2;\n\t"
        "selp.b32 %0, 1, 0, p;\n\t}"
        : "=r"(done) : "r"(mbar), "r"(parity) : "memory");
    while (!done) {
        asm volatile(
            "{\n\t.reg .pred p;\n\t"
            "mbarrier.try_wait.parity.acquire.cluster.shared::cta.b64 p, [%1], %2, 0x989680;\n\t"
            "selp.b32 %0, 1, 0, p;\n\t}"
            : "=r"(done) : "r"(mbar), "r"(parity) : "memory");
    }
}
__device__ __forceinline__ uint32_t mapa_u32(uint32_t laddr, uint32_t rank) {
    uint32_t r;
    asm volatile("mapa.shared::cluster.u32 %0, %1, %2;"
                 : "=r"(r) : "r"(laddr), "r"(rank));
    return r;
}
// remote smem store with tx-count completion on remote mbarrier
__device__ __forceinline__ void st_async_f32(uint32_t raddr, float v, uint32_t rbar) {
    asm volatile(
        "st.async.shared::cluster.mbarrier::complete_tx::bytes.b32 [%0], %1, [%2];"
        :: "r"(raddr), "r"(__float_as_uint(v)), "r"(rbar) : "memory");
}

__device__ __forceinline__ float sigmoidf_(float x) {
    float e = __expf(-fabsf(x));
    float s = __fdividef(1.f, 1.f + e);
    return x >= 0.f ? s : 1.f - s;
}
__device__ __forceinline__ float tanhf_(float x) {
    float e = __expf(-2.f * fabsf(x));
    float t = __fdividef(1.f - e, 1.f + e);
    return x >= 0.f ? t : -t;
}

// ------------------------------ GEMM ---------------------------------------
// out{0,1}[M,N] = A[M,K] @ W{0,1}[N,K]^T + bias{0,1}[N]; z selects direction.
#define BM 64
#define BN 64
#define BK 16

__global__ __launch_bounds__(256) void gemm_bias2_kernel(
    const float* __restrict__ X, const int* __restrict__ idx,
    const float* __restrict__ E,
    const float* __restrict__ W0, const float* __restrict__ bias0,
    float* __restrict__ out0,
    const float* __restrict__ W1, const float* __restrict__ bias1,
    float* __restrict__ out1,
    int M, int N, int K)
{
    __shared__ __align__(16) float As[BK][BM + 4];
    __shared__ __align__(16) float Bs[BK][BN + 4];

    const float* W    = blockIdx.z ? W1    : W0;
    const float* bias = blockIdx.z ? bias1 : bias0;
    float*       out  = blockIdx.z ? out1  : out0;

    int tid = threadIdx.x;
    int m0 = blockIdx.y * BM, n0 = blockIdx.x * BN;
    int lrow = tid >> 2;          // 0..63
    int lcol = (tid & 3) * 4;     // 0,4,8,12
    int tx = tid & 15, ty = tid >> 4;

    float acc[4][4] = {};

    const float* Arow;
    if (idx) Arow = E + (size_t)idx[m0 + lrow] * K;
    else     Arow = X + (size_t)(m0 + lrow) * K;
    const float* Brow = W + (size_t)(n0 + lrow) * K;

    for (int k0 = 0; k0 < K; k0 += BK) {
        float4 av = *(const float4*)(Arow + k0 + lcol);
        float4 bv = *(const float4*)(Brow + k0 + lcol);
        As[lcol + 0][lrow] = av.x; As[lcol + 1][lrow] = av.y;
        As[lcol + 2][lrow] = av.z; As[lcol + 3][lrow] = av.w;
        Bs[lcol + 0][lrow] = bv.x; Bs[lcol + 1][lrow] = bv.y;
        Bs[lcol + 2][lrow] = bv.z; Bs[lcol + 3][lrow] = bv.w;
        __syncthreads();

        #pragma unroll
        for (int kk = 0; kk < BK; kk++) {
            float4 a = *(const float4*)&As[kk][ty * 4];
            float4 b = *(const float4*)&Bs[kk][tx * 4];
            acc[0][0] += a.x * b.x; acc[0][1] += a.x * b.y;
            acc[0][2] += a.x * b.z; acc[0][3] += a.x * b.w;
            acc[1][0] += a.y * b.x; acc[1][1] += a.y * b.y;
            acc[1][2] += a.y * b.z; acc[1][3] += a.y * b.w;
            acc[2][0] += a.z * b.x; acc[2][1] += a.z * b.y;
            acc[2][2] += a.z * b.z; acc[2][3] += a.z * b.w;
            acc[3][0] += a.w * b.x; acc[3][1] += a.w * b.y;
            acc[3][2] += a.w * b.z; acc[3][3] += a.w * b.w;
        }
        __syncthreads();
    }

    #pragma unroll
    for (int i = 0; i < 4; i++) {
        int m = m0 + ty * 4 + i;
        #pragma unroll
        for (int jj = 0; jj < 4; jj++) {
            int n = n0 + tx * 4 + jj;
            out[(size_t)m * N + n] = acc[i][jj] + bias[n];
        }
    }
}

// --------------------------- LSTM recurrence --------------------------------
// Thread map: tid = unit_local*8 + gate*2 + half  (32 units, 4 gates, 2 halves).
// Each 8-lane group owns one hidden unit: gates gathered by width-8 shuffles,
// activations computed redundantly by all 8 lanes, lane k pushes h to rank k
// via st.async with complete_tx on rank k's per-parity mbarrier.
__global__ void __cluster_dims__(CSZ, 1, 1) __launch_bounds__(256, 1)
lstm_layer_kernel(const float* __restrict__ pre_f, const float* __restrict__ pre_b,
                  const float* __restrict__ Whh_f, const float* __restrict__ Whh_b,
                  float* __restrict__ out, int ostride)
{
    __shared__ __align__(16) float hbuf[2][HID];
    __shared__ __align__(8)  uint64_t mbar_store[2];

    int tid  = threadIdx.x;
    int rank = blockIdx.x & (CSZ - 1);
    int dir  = blockIdx.x / CSZ;

    const float* pre = dir ? pre_b : pre_f;
    const float* Whh = dir ? Whh_b : Whh_f;
    int off = dir ? HID : 0;

    int unit = tid >> 3;                 // 0..31 local unit
    int k    = tid & 7;                  // group offset = destination rank
    int gate = k >> 1;                   // 0..3 (i,f,g,o)
    int half = k & 1;                    // K half
    int gr   = gate * HID + rank * 32 + unit;   // gate row (0..1023)
    int u    = rank * 32 + unit;                // global hidden unit

    uint32_t mb0 = smem_u32(&mbar_store[0]);
    uint32_t mb1 = smem_u32(&mbar_store[1]);
    uint32_t hb  = smem_u32(&hbuf[0][0]);

    // load this thread's 128 Whh weights into registers
    float4 w4[32];
    const float4* wsrc = (const float4*)(Whh + (size_t)gr * HID + half * 128);
    #pragma unroll
    for (int i = 0; i < 32; i++) w4[i] = wsrc[i];

    // remote addresses for my h pushes (rank k), per parity
    uint32_t r_h0   = mapa_u32(hb + (uint32_t)u * 4u, (uint32_t)k);
    uint32_t r_h1   = r_h0 + (uint32_t)HID * 4u;
    uint32_t r_mb0  = mapa_u32(mb0, (uint32_t)k);
    uint32_t r_mb1  = r_mb0 + 8u;

    // init: zero BOTH parity buffers (t=0 reads hbuf[1] as h(-1))
    hbuf[0][tid] = 0.f;
    hbuf[1][tid] = 0.f;
    if (tid < 2) mbar_init(tid ? mb1 : mb0, 1);
    __syncthreads();
    if (tid == 0) mbar_expect_tx(mb0, HID * 4);   // expect h(0): 1024 bytes
    CLUSTER_SYNC();                      // inits + expect visible cluster-wide

    float c = 0.f;
    int tt0 = dir ? (TLEN - 1) : 0;
    float pv = __ldg(&pre[tt0 * 1024 + gr]);      // prefetch for t = 0

    for (int t = 0; t < TLEN; t++) {
        if (t > 0) {
            // wait h(t-1): mbar[(t-1)&1], parity ((t-1)>>1)&1
            uint32_t mb = ((t - 1) & 1) ? mb1 : mb0;
            mbar_wait_cluster(mb, (uint32_t)(((t - 1) >> 1) & 1));
        }
        // post expect for h(t+1) one phase ahead; the __syncthreads orders it
        // before any of OUR h(t) stores (which gate remote h(t+1) producers).
        if (t + 1 < TLEN && tid == 0)
            mbar_expect_tx(((t + 1) & 1) ? mb1 : mb0, HID * 4);
        __syncthreads();

        // prefetch pre for t+1 (hidden under the dot)
        float pv_next = 0.f;
        if (t + 1 < TLEN) {
            int tt1 = dir ? (TLEN - 2 - t) : (t + 1);
            pv_next = __ldg(&pre[tt1 * 1024 + gr]);
        }

        int q  = t & 1;        // buffer receiving h(t)
        int qp = q ^ 1;        // buffer holding h(t-1)

        const float4* h4 = (const float4*)&hbuf[qp][half * 128];
        float ax = 0.f, ay = 0.f, az = 0.f, aw = 0.f;
        #pragma unroll
        for (int i = 0; i < 32; i++) {
            float4 hv = h4[i];
            ax += w4[i].x * hv.x; ay += w4[i].y * hv.y;
            az += w4[i].z * hv.z; aw += w4[i].w * hv.w;
        }
        float dot = (ax + ay) + (az + aw);
        dot += __shfl_xor_sync(0xffffffffu, dot, 1);   // combine K halves
        dot += pv;                                     // + input projection

        // gather the 4 gates of this unit into all 8 group lanes
        float gi = __shfl_sync(0xffffffffu, dot, 0, 8);
        float gf = __shfl_sync(0xffffffffu, dot, 2, 8);
        float gg = __shfl_sync(0xffffffffu, dot, 4, 8);
        float go = __shfl_sync(0xffffffffu, dot, 6, 8);

        // redundant (deterministic) activation in all 8 lanes
        c = sigmoidf_(gf) * c + sigmoidf_(gi) * tanhf_(gg);
        float h = sigmoidf_(go) * tanhf_(c);

        int tt = dir ? (TLEN - 1 - t) : t;
        if (k == 0) out[(size_t)tt * ostride + off + u] = h;

        if (t + 1 < TLEN) {
            // push h to rank k's hbuf[q] + signal its mbar[q]
            st_async_f32(q ? r_h1 : r_h0, h, q ? r_mb1 : r_mb0);
        }
        pv = pv_next;
    }
    // no remote traffic after the final wait -> safe to exit without sync
}

// ------------------------------ heads --------------------------------------
__global__ __launch_bounds__(256) void heads_kernel(
    const float* __restrict__ x2, const float* __restrict__ Wm,
    float* __restrict__ sh, float* __restrict__ sd)
{
    int warp = threadIdx.x >> 5, lane = threadIdx.x & 31;
    int row = blockIdx.x * 8 + warp;
    const float4* xr = (const float4*)(x2 + (size_t)row * 512);
    const float4* wh = (const float4*)(Wm);
    const float4* wd = (const float4*)(Wm + 512);
    float a = 0.f, b = 0.f;
    #pragma unroll 4
    for (int i = lane; i < 128; i += 32) {
        float4 xv = xr[i]; float4 hv = wh[i]; float4 dv = wd[i];
        a += xv.x * hv.x + xv.y * hv.y + xv.z * hv.z + xv.w * hv.w;
        b += xv.x * dv.x + xv.y * dv.y + xv.z * dv.z + xv.w * dv.w;
    }
    #pragma unroll
    for (int o = 16; o; o >>= 1) {
        a += __shfl_xor_sync(0xffffffffu, a, o);
        b += __shfl_xor_sync(0xffffffffu, b, o);
    }
    if (lane == 0) { sh[row] = a; sd[row] = b; }
}

// ------------------------------ scores -------------------------------------
__global__ __launch_bounds__(256) void scores_kernel(
    const float* __restrict__ sh, const float* __restrict__ sd,
    const float* __restrict__ bm, float* __restrict__ out)
{
    float bb = __ldg(bm);
    size_t nquad = (size_t)TLEN * TLEN / 4;
    size_t stride = (size_t)gridDim.x * blockDim.x;
    for (size_t idx = (size_t)blockIdx.x * blockDim.x + threadIdx.x;
         idx < nquad; idx += stride) {
        int i  = (int)(idx >> 9);           // row (2048/4 = 512 quads per row)
        int j0 = (int)((idx & 511) << 2);   // first col of quad
        float si = sh[i];
        float4 r;
        r.x = (j0 + 0 > i) ? tanhf(si + sd[j0 + 0] + bb) : 0.f;
        r.y = (j0 + 1 > i) ? tanhf(si + sd[j0 + 1] + bb) : 0.f;
        r.z = (j0 + 2 > i) ? tanhf(si + sd[j0 + 2] + bb) : 0.f;
        r.w = (j0 + 3 > i) ? tanhf(si + sd[j0 + 3] + bb) : 0.f;
        *(float4*)(out + ((size_t)i * TLEN + j0)) = r;
    }
}

// ------------------------------ launch -------------------------------------
extern "C" void kernel_launch(void* const* d_in, const int* in_sizes, int n_in,
                              void* d_out, int out_size)
{
    const int*   word_idx = (const int*)  d_in[0];
    const float* E        = (const float*)d_in[1];
    const float* Wih0f    = (const float*)d_in[2];
    const float* Whh0f    = (const float*)d_in[3];
    const float* b0f      = (const float*)d_in[4];
    const float* Wih0b    = (const float*)d_in[5];
    const float* Whh0b    = (const float*)d_in[6];
    const float* b0b      = (const float*)d_in[7];
    const float* Wih1f    = (const float*)d_in[8];
    const float* Whh1f    = (const float*)d_in[9];
    const float* b1f      = (const float*)d_in[10];
    const float* Wih1b    = (const float*)d_in[11];
    const float* Whh1b    = (const float*)d_in[12];
    const float* b1b      = (const float*)d_in[13];
    const float* Wm       = (const float*)d_in[14];
    const float* bm       = (const float*)d_in[15];
    float* out = (float*)d_out;

    float *pre0f, *pre0b, *pre1f, *pre1b, *x1, *x2, *sh, *sd;
    cudaGetSymbolAddress((void**)&pre0f, g_pre0f);
    cudaGetSymbolAddress((void**)&pre0b, g_pre0b);
    cudaGetSymbolAddress((void**)&pre1f, g_pre1f);
    cudaGetSymbolAddress((void**)&pre1b, g_pre1b);
    cudaGetSymbolAddress((void**)&x1,    g_x1);
    cudaGetSymbolAddress((void**)&x2,    g_x2);
    cudaGetSymbolAddress((void**)&sh,    g_sh);
    cudaGetSymbolAddress((void**)&sd,    g_sd);

    dim3 gg(1024 / BN, TLEN / BM, 2);

    // layer 0 input projection (both directions, fused embedding gather)
    gemm_bias2_kernel<<<gg, 256>>>(nullptr, word_idx, E,
                                   Wih0f, b0f, pre0f, Wih0b, b0b, pre0b,
                                   TLEN, 1024, 256);
    // layer 0 recurrence (fwd + bwd clusters)
    lstm_layer_kernel<<<2 * CSZ, 256>>>(pre0f, pre0b, Whh0f, Whh0b, x1, 512);

    // layer 1 input projection
    gemm_bias2_kernel<<<gg, 256>>>(x1, nullptr, nullptr,
                                   Wih1f, b1f, pre1f, Wih1b, b1b, pre1b,
                                   TLEN, 1024, 512);
    // layer 1 recurrence
    lstm_layer_kernel<<<2 * CSZ, 256>>>(pre1f, pre1b, Whh1f, Whh1b, x2, 512);

    // scoring head
    heads_kernel<<<TLEN / 8, 256>>>(x2, Wm, sh, sd);
    scores_kernel<<<2048, 256>>>(sh, sd, bm, out);
}